// round 15
// baseline (speedup 1.0000x reference)
#include <cuda_runtime.h>

#define N_    1024
#define M_    1024
#define D_    128
#define NNZ_  32768
#define H_    256

typedef unsigned long long u64;

// ---------------- device scratch (no allocations allowed) ----------------
// Zero-initialized at module load; k_sig restores the zero state for
// g_sum / g_cnt after each invocation, so every call sees zeroed scratch.
__device__ int   g_cnt[M_];
__device__ __align__(16) float g_sum[M_ * D_];     // raw scatter sums [m][d]
__device__ __align__(16) float g_hxT[H_ * N_];     // [h][n]
__device__ __align__(16) float g_hebT[H_ * M_];    // [h][m]  (includes /cnt and +b1)

// ---------------- small helpers ----------------
__device__ __forceinline__ u64 bcast2(float v) {
    u64 r;
    asm("mov.b64 %0, {%1, %1};" : "=l"(r) : "f"(v));
    return r;
}

__device__ __forceinline__ float2 unpack2(u64 v) {
    float lo, hi;
    asm("mov.b64 {%0, %1}, %2;" : "=f"(lo), "=f"(hi) : "l"(v));
    return make_float2(lo, hi);
}

// acc2 += relu(a2 + b2) * w2   (packed add/fma; relu on the scalar halves)
__device__ __forceinline__ void relu_fma2(u64 &acc, u64 a, u64 b, u64 w) {
    asm("{\n\t"
        ".reg .b64 t;\n\t"
        ".reg .f32 lo, hi;\n\t"
        "add.rn.f32x2 t, %1, %2;\n\t"
        "mov.b64 {lo, hi}, t;\n\t"
        "max.f32 lo, lo, 0f00000000;\n\t"
        "max.f32 hi, hi, 0f00000000;\n\t"
        "mov.b64 t, {lo, hi};\n\t"
        "fma.rn.f32x2 %0, t, %3, %0;\n\t"
        "}"
        : "+l"(acc) : "l"(a), "l"(b), "l"(w));
}

// sigmoid(x) = 0.5*tanh(0.5x) + 0.5 — single MUFU op
__device__ __forceinline__ float sigmoid_tanh(float x) {
    float t;
    asm("tanh.approx.f32 %0, %1;" : "=f"(t) : "f"(x * 0.5f));
    return fmaf(t, 0.5f, 0.5f);
}

// ---------------- stage 1: scatter (+ init d_out to b2 in extra blocks) --
__global__ __launch_bounds__(256) void k_scatter(const float* __restrict__ X,
                                                 const int* __restrict__ V,
                                                 const int* __restrict__ E,
                                                 const float* __restrict__ b2p,
                                                 float* __restrict__ out) {
    int bx = blockIdx.x;
    if (bx < 1024) {
        float b = b2p[0];
        int i = bx * 256 + threadIdx.x;
        ((float4*)out)[i] = make_float4(b, b, b, b);
        return;
    }
    int edge = (bx - 1024) * 8 + (threadIdx.x >> 5);
    int lane = threadIdx.x & 31;
    int e = E[edge];
    int v = V[edge];
    float4 x = *(const float4*)&X[v * D_ + lane * 4];
    float* dst = &g_sum[e * D_ + lane * 4];
    asm volatile("red.global.add.v4.f32 [%0], {%1, %2, %3, %4};"
                 :: "l"(dst), "f"(x.x), "f"(x.y), "f"(x.z), "f"(x.w) : "memory");
    if (lane == 0) atomicAdd(&g_cnt[e], 1);
}

// ---------------- stage 2: one small GEMM (parameterized z) --------------
// z==0: g_hxT  = (X @ W1[:D]).T                        (independent of scatter)
// z==1: g_hebT = ((g_sum @ W1[D:]) * rcp_cnt).T + b1   (after scatter)
__global__ __launch_bounds__(256) void k_gemm(const float* __restrict__ X,
                                              const float* __restrict__ W1,
                                              const float* __restrict__ b1,
                                              int z) {
    const float* A    = z ? g_sum  : X;
    float*       outT = z ? g_hebT : g_hxT;
    int dof = z ? D_ : 0;

    int n0 = blockIdx.x * 64;
    int h0 = blockIdx.y * 64;

    __shared__ float As[16][65];   // [dk][n]
    __shared__ float Ws[16][64];   // [dk][h]

    int tid = threadIdx.x;
    int tn  = tid & 15;
    int th  = tid >> 4;

    float acc[4][4];
    #pragma unroll
    for (int i = 0; i < 4; i++)
        #pragma unroll
        for (int j = 0; j < 4; j++)
            acc[i][j] = 0.f;

    for (int d0 = 0; d0 < D_; d0 += 16) {
        #pragma unroll
        for (int r = 0; r < 4; r++) {
            int i  = r * 256 + tid;
            int dk = i & 15;
            int nl = i >> 4;
            As[dk][nl] = A[(n0 + nl) * D_ + d0 + dk];
        }
        #pragma unroll
        for (int r = 0; r < 4; r++) {
            int i  = r * 256 + tid;
            int hh = i & 63;
            int dk = i >> 6;
            Ws[dk][hh] = W1[(dof + d0 + dk) * H_ + h0 + hh];
        }
        __syncthreads();
        #pragma unroll
        for (int dk = 0; dk < 16; dk++) {
            float a[4], w[4];
            #pragma unroll
            for (int i = 0; i < 4; i++) a[i] = As[dk][tn * 4 + i];
            #pragma unroll
            for (int j = 0; j < 4; j++) w[j] = Ws[dk][th * 4 + j];
            #pragma unroll
            for (int i = 0; i < 4; i++)
                #pragma unroll
                for (int j = 0; j < 4; j++)
                    acc[i][j] = fmaf(a[i], w[j], acc[i][j]);
        }
        __syncthreads();
    }

    float scale[4] = {1.f, 1.f, 1.f, 1.f};
    if (z) {
        #pragma unroll
        for (int i = 0; i < 4; i++) {
            int c = g_cnt[n0 + tn * 4 + i];
            scale[i] = 1.0f / ((c > 0) ? (float)c : 1.0f);
        }
    }
    #pragma unroll
    for (int j = 0; j < 4; j++) {
        int h = h0 + th * 4 + j;
        float bb = z ? b1[h] : 0.f;
        float4 v = make_float4(acc[0][j] * scale[0] + bb,
                               acc[1][j] * scale[1] + bb,
                               acc[2][j] * scale[2] + bb,
                               acc[3][j] * scale[3] + bb);
        *(float4*)&outT[h * N_ + n0 + tn * 4] = v;
    }
}

// ---------------- stage 3: main N x M x H contraction (h-split) ----------
// grid (H/64, M/64, N/64) = 1024 blocks, 128 threads, all co-resident.
__global__ __launch_bounds__(128, 7) void k_main(const float* __restrict__ W2,
                                                 float* __restrict__ out) {
    __shared__ __align__(16) float hx_s[32][64];
    __shared__ __align__(16) float heb_s[32][64];
    __shared__ float w2_s[64];

    int hb = blockIdx.x * 64;
    int m0 = blockIdx.y * 64;
    int n0 = blockIdx.z * 64;
    int tid = threadIdx.x;
    int tn  = tid & 15;   // n base = tn*4
    int tm  = tid >> 4;   // m base = tm*8

    u64 acc[4][4];        // [ni][mpair]
    #pragma unroll
    for (int i = 0; i < 4; i++)
        #pragma unroll
        for (int p = 0; p < 4; p++)
            acc[i][p] = 0ull;

    if (tid < 64) w2_s[tid] = W2[hb + tid];

    int cg = tid & 15;    // float4 column group for loads
    int r0 = tid >> 4;    // row base for loads (0..7)

    for (int sc = 0; sc < 2; sc++) {
        int hbase = hb + sc * 32;
        #pragma unroll
        for (int k = 0; k < 4; k++) {
            int hh = k * 8 + r0;
            *(float4*)&hx_s[hh][cg * 4]  = *(const float4*)&g_hxT[(hbase + hh) * N_ + n0 + cg * 4];
            *(float4*)&heb_s[hh][cg * 4] = *(const float4*)&g_hebT[(hbase + hh) * M_ + m0 + cg * 4];
        }
        __syncthreads();

        #pragma unroll 4
        for (int hh = 0; hh < 32; hh++) {
            float4 hx4 = *(const float4*)&hx_s[hh][tn * 4];
            ulonglong2 e0 = *(const ulonglong2*)&heb_s[hh][tm * 8];
            ulonglong2 e1 = *(const ulonglong2*)&heb_s[hh][tm * 8 + 4];
            u64 w2p = bcast2(w2_s[sc * 32 + hh]);
            u64 q0 = bcast2(hx4.x);
            u64 q1 = bcast2(hx4.y);
            u64 q2 = bcast2(hx4.z);
            u64 q3 = bcast2(hx4.w);

            relu_fma2(acc[0][0], e0.x, q0, w2p);
            relu_fma2(acc[0][1], e0.y, q0, w2p);
            relu_fma2(acc[0][2], e1.x, q0, w2p);
            relu_fma2(acc[0][3], e1.y, q0, w2p);

            relu_fma2(acc[1][0], e0.x, q1, w2p);
            relu_fma2(acc[1][1], e0.y, q1, w2p);
            relu_fma2(acc[1][2], e1.x, q1, w2p);
            relu_fma2(acc[1][3], e1.y, q1, w2p);

            relu_fma2(acc[2][0], e0.x, q2, w2p);
            relu_fma2(acc[2][1], e0.y, q2, w2p);
            relu_fma2(acc[2][2], e1.x, q2, w2p);
            relu_fma2(acc[2][3], e1.y, q2, w2p);

            relu_fma2(acc[3][0], e0.x, q3, w2p);
            relu_fma2(acc[3][1], e0.y, q3, w2p);
            relu_fma2(acc[3][2], e1.x, q3, w2p);
            relu_fma2(acc[3][3], e1.y, q3, w2p);
        }
        __syncthreads();
    }

    // epilogue: vector-RED partial logits into out[n][m] (on top of b2 init)
    #pragma unroll
    for (int i = 0; i < 4; i++) {
        int n = n0 + tn * 4 + i;
        float2 a = unpack2(acc[i][0]);
        float2 b = unpack2(acc[i][1]);
        float2 c = unpack2(acc[i][2]);
        float2 d = unpack2(acc[i][3]);
        float* dst = &out[n * M_ + m0 + tm * 8];
        asm volatile("red.global.add.v4.f32 [%0], {%1, %2, %3, %4};"
                     :: "l"(dst), "f"(a.x), "f"(a.y), "f"(b.x), "f"(b.y) : "memory");
        asm volatile("red.global.add.v4.f32 [%0], {%1, %2, %3, %4};"
                     :: "l"(dst + 4), "f"(c.x), "f"(c.y), "f"(d.x), "f"(d.y) : "memory");
    }
}

// ---------------- stage 4: sigmoid epilogue (tanh.approx) + re-zero ------
__global__ __launch_bounds__(256) void k_sig(float* __restrict__ out) {
    int tid  = threadIdx.x;
    int base = blockIdx.x * 512 + tid;      // float4 index
    float4* o4 = (float4*)out;

    float4 v0 = o4[base];
    float4 v1 = o4[base + 256];

    int i = blockIdx.x * 256 + tid;
    if (i < (M_ * D_) / 4) ((float4*)g_sum)[i] = make_float4(0.f, 0.f, 0.f, 0.f);
    if (i < M_) g_cnt[i] = 0;

    v0.x = sigmoid_tanh(v0.x);
    v0.y = sigmoid_tanh(v0.y);
    v0.z = sigmoid_tanh(v0.z);
    v0.w = sigmoid_tanh(v0.w);
    v1.x = sigmoid_tanh(v1.x);
    v1.y = sigmoid_tanh(v1.y);
    v1.z = sigmoid_tanh(v1.z);
    v1.w = sigmoid_tanh(v1.w);

    o4[base]       = v0;
    o4[base + 256] = v1;
}

// ---------------- launch: fork gemm_z0 parallel to scatter ----------------
extern "C" void kernel_launch(void* const* d_in, const int* in_sizes, int n_in,
                              void* d_out, int out_size) {
    const float* X  = (const float*)d_in[0];
    const int*   V  = (const int*)d_in[1];
    const int*   E  = (const int*)d_in[2];
    const float* W1 = (const float*)d_in[3];
    const float* b1 = (const float*)d_in[4];
    const float* W2 = (const float*)d_in[5];
    const float* b2 = (const float*)d_in[6];
    float* out = (float*)d_out;

    cudaStream_t s2;
    cudaEvent_t  eFork, eJoin;
    cudaStreamCreateWithFlags(&s2, cudaStreamNonBlocking);
    cudaEventCreateWithFlags(&eFork, cudaEventDisableTiming);
    cudaEventCreateWithFlags(&eJoin, cudaEventDisableTiming);

    // fork: gemm_z0 (hxT = X@W1a) runs concurrent with scatter
    cudaEventRecord(eFork, 0);
    cudaStreamWaitEvent(s2, eFork, 0);
    k_gemm<<<dim3(N_ / 64, H_ / 64, 1), 256, 0, s2>>>(X, W1, b1, 0);
    cudaEventRecord(eJoin, s2);

    // main stream: scatter -> gemm_z1 (hebT, depends on scatter)
    k_scatter<<<1024 + NNZ_ / 8, 256>>>(X, V, E, b2, out);
    k_gemm<<<dim3(N_ / 64, H_ / 64, 1), 256>>>(X, W1, b1, 1);

    // join: k_main needs both branches
    cudaStreamWaitEvent(0, eJoin, 0);
    k_main<<<dim3(H_ / 64, M_ / 64, N_ / 64), 128>>>(W2, out);
    k_sig<<<512, 256>>>(out);

    cudaEventDestroy(eFork);
    cudaEventDestroy(eJoin);
    cudaStreamDestroy(s2);
}